// round 2
// baseline (speedup 1.0000x reference)
#include <cuda_runtime.h>
#include <math.h>

// Problem constants
#define L     4096
#define NF    4097          // rfft bins for n=8192
#define NFFT  8192
#define DIN   64
#define DOUT  64
#define KF    40
#define BSZ   2
#define FT    16            // frequency tile in einsum kernel

typedef unsigned long long ull;

// ---------------- static device scratch (no allocations allowed) ----------------
__device__ float2 g_Xf[BSZ * NF * DIN];    // rfft of x          (~4.2 MB)
__device__ float2 g_vf[NF * KF];           // rfft of phi        (~1.3 MB)
__device__ float2 g_Sp[BSZ * NF * DOUT];   // plus-branch spectrum
__device__ float2 g_Sm[BSZ * NF * DOUT];   // minus-branch spectrum

// ---------------- helpers ----------------
__device__ __forceinline__ unsigned brev13(unsigned i) { return __brev(i) >> 19; }

__device__ __forceinline__ ull pack2(float x, float y) {
    ull r; asm("mov.b64 %0, {%1, %2};" : "=l"(r) : "f"(x), "f"(y)); return r;
}
__device__ __forceinline__ ull dup2(float a) {
    ull r; asm("mov.b64 %0, {%1, %1};" : "=l"(r) : "f"(a)); return r;
}
__device__ __forceinline__ ull fma2(ull a, ull b, ull c) {
    ull r; asm("fma.rn.f32x2 %0, %1, %2, %3;" : "=l"(r) : "l"(a), "l"(b), "l"(c)); return r;
}
__device__ __forceinline__ float2 unpack2(ull v) {
    float x, y; asm("mov.b64 {%0, %1}, %2;" : "=f"(x), "=f"(y) : "l"(v));
    return make_float2(x, y);
}

// In-place radix-2 DIT FFT of length 8192 in shared memory.
// Input must be stored in bit-reversed order. SIGN=-1 forward, +1 inverse (unscaled).
template<int SIGN>
__device__ __forceinline__ void fft8192(float2* s) {
    #pragma unroll
    for (int st = 0; st < 13; ++st) {
        const int   half = 1 << st;
        const float ang  = (float)SIGN * 3.14159265358979323846f / (float)half;
        for (int j = threadIdx.x; j < 4096; j += 256) {
            int pos = j & (half - 1);
            int i0  = ((j >> st) << (st + 1)) + pos;
            int i1  = i0 + half;
            float sw, cw;
            __sincosf(ang * (float)pos, &sw, &cw);
            float2 u = s[i0], v = s[i1];
            float tr = cw * v.x - sw * v.y;
            float ti = cw * v.y + sw * v.x;
            s[i0] = make_float2(u.x + tr, u.y + ti);
            s[i1] = make_float2(u.x - tr, u.y - ti);
        }
        __syncthreads();
    }
}

// ---------------- K1: forward FFT of x (two real columns packed per complex FFT) ----------------
__global__ void k_fft_x(const float* __restrict__ x) {
    extern __shared__ float2 s[];
    const int b  = blockIdx.x >> 5;
    const int d0 = (blockIdx.x & 31) * 2;
    const float* xb = x + (size_t)b * L * DIN + d0;

    for (int i = threadIdx.x; i < NFFT; i += 256) {
        float2 z = make_float2(0.f, 0.f);
        if (i < L) z = *(const float2*)(xb + (size_t)i * DIN);
        s[brev13(i)] = z;
    }
    __syncthreads();
    fft8192<-1>(s);

    float2* Xb = g_Xf + (size_t)b * NF * DIN;
    for (int f = threadIdx.x; f <= L; f += 256) {
        float2 P = s[f];
        float2 Q = s[(NFFT - f) & (NFFT - 1)];
        float qr = Q.x, qi = -Q.y;   // conj
        float2 A  = make_float2(0.5f * (P.x + qr),  0.5f * (P.y + qi));   // col d0
        float2 Bv = make_float2(0.5f * (P.y - qi), -0.5f * (P.x - qr));   // col d0+1
        *(float4*)(&Xb[(size_t)f * DIN + d0]) = make_float4(A.x, A.y, Bv.x, Bv.y);
    }
}

// ---------------- K2: forward FFT of phi (two filters packed) ----------------
__global__ void k_fft_phi(const float* __restrict__ phi) {
    extern __shared__ float2 s[];
    const int k0 = blockIdx.x * 2;

    for (int i = threadIdx.x; i < NFFT; i += 256) {
        float2 z = make_float2(0.f, 0.f);
        if (i < L) z = *(const float2*)(phi + (size_t)i * KF + k0);
        s[brev13(i)] = z;
    }
    __syncthreads();
    fft8192<-1>(s);

    for (int f = threadIdx.x; f <= L; f += 256) {
        float2 P = s[f];
        float2 Q = s[(NFFT - f) & (NFFT - 1)];
        float qr = Q.x, qi = -Q.y;
        float2 A  = make_float2(0.5f * (P.x + qr),  0.5f * (P.y + qi));
        float2 Bv = make_float2(0.5f * (P.y - qi), -0.5f * (P.x - qr));
        *(float4*)(&g_vf[(size_t)f * KF + k0]) = make_float4(A.x, A.y, Bv.x, Bv.y);
    }
}

// ---------------- K3: frequency-domain contraction ----------------
// Sp[b,f,o] = sum_k vf[f,k] * sum_d Xf[b,f,d]        * Mp[k,d,o]
// Sm[b,f,o] = sum_k vf[f,k] * sum_d conj(Xf[b,L-f,d])* Mm[k,d,o]
__global__ __launch_bounds__(256, 2)
void k_einsum(const float* __restrict__ Mp, const float* __restrict__ Mm) {
    __shared__ ull    XP[FT][2 * DIN];
    __shared__ ull    XM[FT][2 * DIN];
    __shared__ float2 VF[FT][KF];

    const int f0 = blockIdx.x * FT;

    for (int idx = threadIdx.x; idx < FT * 2 * DIN; idx += 256) {
        int fl = idx >> 7, c = idx & 127;
        int b = c >> 6, d = c & 63;
        int f = f0 + fl;
        ull xp = 0ull, xm = 0ull;
        if (f <= L) {
            float2 t1 = g_Xf[((size_t)b * NF + f) * DIN + d];
            float2 t2 = g_Xf[((size_t)b * NF + (L - f)) * DIN + d];
            xp = pack2(t1.x, t1.y);
            xm = pack2(t2.x, -t2.y);      // conj
        }
        XP[fl][c] = xp;
        XM[fl][c] = xm;
    }
    for (int idx = threadIdx.x; idx < FT * KF; idx += 256) {
        int fl = idx / KF, k = idx - fl * KF;
        int f  = f0 + fl;
        VF[fl][k] = (f <= L) ? g_vf[(size_t)f * KF + k] : make_float2(0.f, 0.f);
    }
    __syncthreads();

    const int fl = threadIdx.x >> 4;     // 0..15 : frequency within tile
    const int og = threadIdx.x & 15;     // 0..15 : group of 4 output channels
    const int f  = f0 + fl;

    float2 aP[8], aM[8];
    #pragma unroll
    for (int i = 0; i < 8; ++i) { aP[i] = make_float2(0.f, 0.f); aM[i] = make_float2(0.f, 0.f); }

    const ull* xpf = XP[fl];
    const ull* xmf = XM[fl];

    for (int k = 0; k < KF; ++k) {
        float2 v = VF[fl][k];
        ull Tp[8], Tm[8];
        #pragma unroll
        for (int i = 0; i < 8; ++i) { Tp[i] = 0ull; Tm[i] = 0ull; }

        const float* mp = Mp + k * 4096 + og * 4;
        const float* mm = Mm + k * 4096 + og * 4;

        #pragma unroll 8
        for (int d = 0; d < 64; ++d) {
            float4 a  = *(const float4*)(mp + d * 64);
            float4 cc = *(const float4*)(mm + d * 64);
            ull x0 = xpf[d], x1 = xpf[64 + d];
            ull y0 = xmf[d], y1 = xmf[64 + d];

            ull a0 = dup2(a.x), a1 = dup2(a.y), a2 = dup2(a.z), a3 = dup2(a.w);
            Tp[0] = fma2(x0, a0, Tp[0]);
            Tp[1] = fma2(x0, a1, Tp[1]);
            Tp[2] = fma2(x0, a2, Tp[2]);
            Tp[3] = fma2(x0, a3, Tp[3]);
            Tp[4] = fma2(x1, a0, Tp[4]);
            Tp[5] = fma2(x1, a1, Tp[5]);
            Tp[6] = fma2(x1, a2, Tp[6]);
            Tp[7] = fma2(x1, a3, Tp[7]);

            ull c0 = dup2(cc.x), c1 = dup2(cc.y), c2 = dup2(cc.z), c3 = dup2(cc.w);
            Tm[0] = fma2(y0, c0, Tm[0]);
            Tm[1] = fma2(y0, c1, Tm[1]);
            Tm[2] = fma2(y0, c2, Tm[2]);
            Tm[3] = fma2(y0, c3, Tm[3]);
            Tm[4] = fma2(y1, c0, Tm[4]);
            Tm[5] = fma2(y1, c1, Tm[5]);
            Tm[6] = fma2(y1, c2, Tm[6]);
            Tm[7] = fma2(y1, c3, Tm[7]);
        }

        #pragma unroll
        for (int i = 0; i < 8; ++i) {
            float2 t = unpack2(Tp[i]);
            aP[i].x += v.x * t.x - v.y * t.y;
            aP[i].y += v.x * t.y + v.y * t.x;
            float2 u = unpack2(Tm[i]);
            aM[i].x += v.x * u.x - v.y * u.y;
            aM[i].y += v.x * u.y + v.y * u.x;
        }
    }

    if (f <= L) {
        #pragma unroll
        for (int b = 0; b < 2; ++b) {
            #pragma unroll
            for (int j = 0; j < 4; ++j) {
                size_t base = ((size_t)b * NF + f) * DOUT + og * 4 + j;
                g_Sp[base] = aP[b * 4 + j];
                g_Sm[base] = aM[b * 4 + j];
            }
        }
    }
}

// ---------------- K4: inverse FFT; Re -> plus branch, Im -> minus branch ----------------
__global__ void k_ifft(float* __restrict__ out) {
    extern __shared__ float2 s[];
    const int b = blockIdx.x >> 6;
    const int o = blockIdx.x & 63;
    const float2* spb = g_Sp + (size_t)b * NF * DOUT + o;
    const float2* smb = g_Sm + (size_t)b * NF * DOUT + o;

    // Build full 8192 spectrum: C = SpExt + i*SmExt (Hermitian extension of both)
    for (int f = threadIdx.x; f < NFFT; f += 256) {
        float2 C;
        if (f <= L) {
            float2 p = spb[(size_t)f * DOUT];
            float2 m = smb[(size_t)f * DOUT];
            C = make_float2(p.x - m.y, p.y + m.x);
        } else {
            int g = NFFT - f;
            float2 p = spb[(size_t)g * DOUT];
            float2 m = smb[(size_t)g * DOUT];
            C = make_float2(p.x + m.y, m.x - p.y);
        }
        s[brev13(f)] = C;
    }
    __syncthreads();
    fft8192<1>(s);

    const float inv = 1.0f / (float)NFFT;
    float* ob = out + (size_t)b * L * DOUT + o;
    for (int t = threadIdx.x; t < L; t += 256) {
        float2 c = s[t];
        float sg = (t & 1) ? -1.f : 1.f;
        ob[(size_t)t * DOUT] = inv * (c.x + sg * c.y);
    }
}

// ---------------- K5: autoregressive term, out += sum_i M[:,:,i] @ x[t-i] ----------------
#define AR_T 128
__global__ __launch_bounds__(256)
void k_ar(const float* __restrict__ x, const float* __restrict__ M, float* __restrict__ out) {
    extern __shared__ float sm[];
    float* Ms = sm;              // [3][64][64] -> Ms[(i*64+d)*64 + o], 12288 floats
    float* xs = sm + 12288;      // [130][64] rows t0-2 .. t0+127, 8320 floats

    const int b  = blockIdx.x >> 5;
    const int t0 = (blockIdx.x & 31) * AR_T;

    for (int idx = threadIdx.x; idx < 12288; idx += 256) {
        int o = idx / 192, r = idx - o * 192;
        int d = r / 3, i = r - d * 3;
        Ms[(i * 64 + d) * 64 + o] = M[idx];
    }
    for (int idx = threadIdx.x; idx < 130 * 64; idx += 256) {
        int r = idx >> 6, d = idx & 63;
        int t = t0 - 2 + r;
        xs[idx] = (t >= 0) ? x[((size_t)b * L + t) * DIN + d] : 0.f;
    }
    __syncthreads();

    const int o  = threadIdx.x & 63;
    const int tg = threadIdx.x >> 6;
    for (int tl = tg; tl < AR_T; tl += 4) {
        const float* x0 = xs + (tl + 2) * 64;   // x[t]
        const float* x1 = x0 - 64;              // x[t-1]
        const float* x2 = x0 - 128;             // x[t-2]
        float acc = 0.f;
        #pragma unroll
        for (int d = 0; d < 64; ++d) {
            acc += Ms[d * 64 + o]        * x0[d];
            acc += Ms[4096 + d * 64 + o] * x1[d];
            acc += Ms[8192 + d * 64 + o] * x2[d];
        }
        out[((size_t)b * L + t0 + tl) * DOUT + o] += acc;
    }
}

// ---------------- launch ----------------
extern "C" void kernel_launch(void* const* d_in, const int* in_sizes, int n_in,
                              void* d_out, int out_size) {
    const float* x   = (const float*)d_in[0];
    const float* phi = (const float*)d_in[1];
    const float* M   = (const float*)d_in[2];
    const float* Mp  = (const float*)d_in[3];
    const float* Mm  = (const float*)d_in[4];
    float* out = (float*)d_out;

    const int FFT_SMEM = NFFT * sizeof(float2);        // 65536
    const int AR_SMEM  = (12288 + 130 * 64) * 4;       // 82432

    cudaFuncSetAttribute(k_fft_x,   cudaFuncAttributeMaxDynamicSharedMemorySize, FFT_SMEM);
    cudaFuncSetAttribute(k_fft_phi, cudaFuncAttributeMaxDynamicSharedMemorySize, FFT_SMEM);
    cudaFuncSetAttribute(k_ifft,    cudaFuncAttributeMaxDynamicSharedMemorySize, FFT_SMEM);
    cudaFuncSetAttribute(k_ar,      cudaFuncAttributeMaxDynamicSharedMemorySize, AR_SMEM);

    k_fft_x  <<<BSZ * (DIN / 2), 256, FFT_SMEM>>>(x);
    k_fft_phi<<<KF / 2,          256, FFT_SMEM>>>(phi);
    k_einsum <<<(NF + FT - 1) / FT, 256>>>(Mp, Mm);
    k_ifft   <<<BSZ * DOUT,      256, FFT_SMEM>>>(out);
    k_ar     <<<BSZ * (L / AR_T), 256, AR_SMEM>>>(x, M, out);
}

// round 3
// speedup vs baseline: 1.6959x; 1.6959x over previous
#include <cuda_runtime.h>
#include <math.h>

// Problem constants
#define L     4096
#define NF    4097          // rfft bins for n=8192
#define NFFT  8192
#define DIN   64
#define DOUT  64
#define KF    40
#define BSZ   2
#define FE    32            // frequencies per einsum block

// ---------------- static device scratch (no allocations allowed) ----------------
__device__ float2 g_Xf[BSZ * NF * DIN];    // rfft of x
__device__ float2 g_vf[NF * KF];           // rfft of phi
__device__ float2 g_Sp[BSZ * NF * DOUT];   // plus-branch spectrum
__device__ float2 g_Sm[BSZ * NF * DOUT];   // minus-branch spectrum

// ---------------- helpers ----------------
__device__ __forceinline__ unsigned brev13(unsigned i) { return __brev(i) >> 19; }

__device__ __forceinline__ unsigned tf32cvt(float x) {
    unsigned r; asm("cvt.rna.tf32.f32 %0, %1;" : "=r"(r) : "f"(x)); return r;
}

__device__ __forceinline__ void mma_tf32(float& d0, float& d1, float& d2, float& d3,
                                         unsigned a0, unsigned a1, unsigned a2, unsigned a3,
                                         unsigned b0, unsigned b1) {
    asm("mma.sync.aligned.m16n8k8.row.col.f32.tf32.tf32.f32 "
        "{%0,%1,%2,%3},{%4,%5,%6,%7},{%8,%9},{%0,%1,%2,%3};"
        : "+f"(d0), "+f"(d1), "+f"(d2), "+f"(d3)
        : "r"(a0), "r"(a1), "r"(a2), "r"(a3), "r"(b0), "r"(b1));
}

// In-place radix-2 DIT FFT of length 8192 in shared memory (bit-reversed input).
template<int SIGN, int NT>
__device__ __forceinline__ void fft8192(float2* s) {
    #pragma unroll
    for (int st = 0; st < 13; ++st) {
        const int   half = 1 << st;
        const float ang  = (float)SIGN * 3.14159265358979323846f / (float)half;
        for (int j = threadIdx.x; j < 4096; j += NT) {
            int pos = j & (half - 1);
            int i0  = ((j >> st) << (st + 1)) + pos;
            int i1  = i0 + half;
            float sw, cw;
            __sincosf(ang * (float)pos, &sw, &cw);
            float2 u = s[i0], v = s[i1];
            float tr = cw * v.x - sw * v.y;
            float ti = cw * v.y + sw * v.x;
            s[i0] = make_float2(u.x + tr, u.y + ti);
            s[i1] = make_float2(u.x - tr, u.y - ti);
        }
        __syncthreads();
    }
}

// ---------------- K1: forward FFT of x (two real columns per complex FFT) ----------------
__global__ __launch_bounds__(1024) void k_fft_x(const float* __restrict__ x) {
    extern __shared__ float2 s[];
    const int b  = blockIdx.x >> 5;
    const int d0 = (blockIdx.x & 31) * 2;
    const float* xb = x + (size_t)b * L * DIN + d0;

    for (int i = threadIdx.x; i < NFFT; i += 1024) {
        float2 z = make_float2(0.f, 0.f);
        if (i < L) z = *(const float2*)(xb + (size_t)i * DIN);
        s[brev13(i)] = z;
    }
    __syncthreads();
    fft8192<-1, 1024>(s);

    float2* Xb = g_Xf + (size_t)b * NF * DIN;
    for (int f = threadIdx.x; f <= L; f += 1024) {
        float2 P = s[f];
        float2 Q = s[(NFFT - f) & (NFFT - 1)];
        float qr = Q.x, qi = -Q.y;
        float2 A  = make_float2(0.5f * (P.x + qr),  0.5f * (P.y + qi));
        float2 Bv = make_float2(0.5f * (P.y - qi), -0.5f * (P.x - qr));
        *(float4*)(&Xb[(size_t)f * DIN + d0]) = make_float4(A.x, A.y, Bv.x, Bv.y);
    }
}

// ---------------- K2: forward FFT of phi (two filters packed) ----------------
__global__ __launch_bounds__(1024) void k_fft_phi(const float* __restrict__ phi) {
    extern __shared__ float2 s[];
    const int k0 = blockIdx.x * 2;

    for (int i = threadIdx.x; i < NFFT; i += 1024) {
        float2 z = make_float2(0.f, 0.f);
        if (i < L) z = *(const float2*)(phi + (size_t)i * KF + k0);
        s[brev13(i)] = z;
    }
    __syncthreads();
    fft8192<-1, 1024>(s);

    for (int f = threadIdx.x; f <= L; f += 1024) {
        float2 P = s[f];
        float2 Q = s[(NFFT - f) & (NFFT - 1)];
        float qr = Q.x, qi = -Q.y;
        float2 A  = make_float2(0.5f * (P.x + qr),  0.5f * (P.y + qi));
        float2 Bv = make_float2(0.5f * (P.y - qi), -0.5f * (P.x - qr));
        *(float4*)(&g_vf[(size_t)f * KF + k0]) = make_float4(A.x, A.y, Bv.x, Bv.y);
    }
}

// ---------------- K3: frequency-domain contraction via tf32 mma.sync ----------------
// Sp[b,f,o] = sum_k vf[f,k] * sum_d Xf[b,f,d]        * Mp[k,d,o]
// Sm[b,f,o] = sum_k vf[f,k] * sum_d conj(Xf[b,L-f,d])* Mm[k,d,o]
//
// Per block: 32 freqs x 2 batches = 64 (b,f) pairs -> 128 GEMM rows ({re,im}).
// Row layout: warp w owns rows [16w,16w+16); within the 16-row tile, row q = re of
// pair 8w+q, row q+8 = im of same pair (so mma accum c0/c1 + c2/c3 form the re/im
// pair in ONE thread -> shuffle-free complex rotation by v[f,k] per k).
// X split into tf32 hi+lo (exact); M rounded to tf32 once.
#define SA 68   // A smem row stride (floats) — conflict-free frag loads
#define SB 72   // B smem row stride (floats) — conflict-free frag loads

__global__ __launch_bounds__(256, 1)
void k_einsum(const float* __restrict__ Mp, const float* __restrict__ Mm) {
    extern __shared__ float sm[];
    float*  Ah = sm;                       // [128][SA]
    float*  Al = Ah + 128 * SA;            // [128][SA]
    float*  Bs = Al + 128 * SA;            // [2][64][SB]
    float2* Vs = (float2*)(Bs + 2 * 64 * SB);  // [FE][KF]

    const int tid  = threadIdx.x;
    const int w    = tid >> 5;
    const int lane = tid & 31;
    const int g    = lane >> 2;      // 0..7
    const int tg   = lane & 3;       // 0..3
    const int f0   = blockIdx.x * FE;

    // stage V (complex filter spectra for this tile)
    for (int idx = tid; idx < FE * KF; idx += 256) {
        int fl = idx / KF, k = idx - fl * KF;
        int f  = f0 + fl;
        Vs[fl * KF + k] = (f <= L) ? g_vf[(size_t)f * KF + k] : make_float2(0.f, 0.f);
    }

    const int  p   = 8 * w + g;          // this thread's (b,f) pair
    const int  pfl = p & 31;
    const int  pb  = p >> 5;
    const int  pf  = f0 + pfl;
    const float2 zv = make_float2(0.f, 0.f);

    for (int br = 0; br < 2; ++br) {
        const float* Mb = br ? Mm : Mp;
        __syncthreads();                 // As reuse / Vs ready

        // ---- build split A in smem ----
        for (int idx = tid; idx < 64 * 64; idx += 256) {
            int pp = idx >> 6, d = idx & 63;
            int b  = pp >> 5, fl = pp & 31;
            int f  = f0 + fl;
            float re = 0.f, im = 0.f;
            if (f <= L) {
                float2 X;
                if (br == 0) { X = g_Xf[((size_t)b * NF + f) * DIN + d];       re = X.x; im = X.y;  }
                else         { X = g_Xf[((size_t)b * NF + (L - f)) * DIN + d]; re = X.x; im = -X.y; }
            }
            int rr = ((pp >> 3) << 4) + (pp & 7);     // re row
            unsigned hb = tf32cvt(re);
            float    hf = __uint_as_float(hb);
            unsigned lb = tf32cvt(re - hf);
            Ah[rr * SA + d] = hf;
            Al[rr * SA + d] = __uint_as_float(lb);
            hb = tf32cvt(im);
            hf = __uint_as_float(hb);
            lb = tf32cvt(im - hf);
            Ah[(rr + 8) * SA + d] = hf;
            Al[(rr + 8) * SA + d] = __uint_as_float(lb);
        }
        __syncthreads();

        // ---- load A fragments into registers (persist across k loop) ----
        unsigned ah[8][4], al[8][4];
        const int ar = w * 16 + g;
        #pragma unroll
        for (int ks = 0; ks < 8; ++ks) {
            int c = 8 * ks + tg;
            ah[ks][0] = __float_as_uint(Ah[ar * SA + c]);
            ah[ks][1] = __float_as_uint(Ah[(ar + 8) * SA + c]);
            ah[ks][2] = __float_as_uint(Ah[ar * SA + c + 4]);
            ah[ks][3] = __float_as_uint(Ah[(ar + 8) * SA + c + 4]);
            al[ks][0] = __float_as_uint(Al[ar * SA + c]);
            al[ks][1] = __float_as_uint(Al[(ar + 8) * SA + c]);
            al[ks][2] = __float_as_uint(Al[ar * SA + c + 4]);
            al[ks][3] = __float_as_uint(Al[(ar + 8) * SA + c + 4]);
        }

        float S[8][4];
        #pragma unroll
        for (int nt = 0; nt < 8; ++nt)
            S[nt][0] = S[nt][1] = S[nt][2] = S[nt][3] = 0.f;

        // ---- stage B for k=0 ----
        {
            const float* src = Mb;
            #pragma unroll
            for (int i = 0; i < 4; ++i) {
                int e = (tid + i * 256) * 4;
                float4 v4 = *(const float4*)(src + e);
                v4.x = __uint_as_float(tf32cvt(v4.x));
                v4.y = __uint_as_float(tf32cvt(v4.y));
                v4.z = __uint_as_float(tf32cvt(v4.z));
                v4.w = __uint_as_float(tf32cvt(v4.w));
                *(float4*)(&Bs[(e >> 6) * SB + (e & 63)]) = v4;
            }
        }
        __syncthreads();

        // ---- main k loop with double-buffered B ----
        for (int k = 0; k < KF; ++k) {
            const int cur = k & 1;
            float4 pf4[4];
            if (k + 1 < KF) {
                const float* src = Mb + (size_t)(k + 1) * 4096;
                #pragma unroll
                for (int i = 0; i < 4; ++i) {
                    int e = (tid + i * 256) * 4;
                    pf4[i] = *(const float4*)(src + e);
                }
            }

            const float* Bc = Bs + cur * 64 * SB;
            const float2 v  = (pf <= L) ? Vs[pfl * KF + k] : zv;

            #pragma unroll
            for (int nt = 0; nt < 8; ++nt) {
                float t0 = 0.f, t1 = 0.f, t2 = 0.f, t3 = 0.f;
                const int nc = 8 * nt + g;
                #pragma unroll
                for (int ks = 0; ks < 8; ++ks) {
                    unsigned b0 = __float_as_uint(Bc[(8 * ks + tg) * SB + nc]);
                    unsigned b1 = __float_as_uint(Bc[(8 * ks + tg + 4) * SB + nc]);
                    mma_tf32(t0, t1, t2, t3, ah[ks][0], ah[ks][1], ah[ks][2], ah[ks][3], b0, b1);
                    mma_tf32(t0, t1, t2, t3, al[ks][0], al[ks][1], al[ks][2], al[ks][3], b0, b1);
                }
                S[nt][0] += v.x * t0 - v.y * t2;
                S[nt][1] += v.x * t1 - v.y * t3;
                S[nt][2] += v.x * t2 + v.y * t0;
                S[nt][3] += v.x * t3 + v.y * t1;
            }

            if (k + 1 < KF) {
                float* Bn = Bs + (cur ^ 1) * 64 * SB;
                #pragma unroll
                for (int i = 0; i < 4; ++i) {
                    int e = (tid + i * 256) * 4;
                    float4 v4 = pf4[i];
                    v4.x = __uint_as_float(tf32cvt(v4.x));
                    v4.y = __uint_as_float(tf32cvt(v4.y));
                    v4.z = __uint_as_float(tf32cvt(v4.z));
                    v4.w = __uint_as_float(tf32cvt(v4.w));
                    *(float4*)(&Bn[(e >> 6) * SB + (e & 63)]) = v4;
                }
            }
            __syncthreads();
        }

        // ---- store S ----
        if (pf <= L) {
            float2* Sg = (br ? g_Sm : g_Sp) + ((size_t)pb * NF + pf) * DOUT;
            #pragma unroll
            for (int nt = 0; nt < 8; ++nt) {
                int o = 8 * nt + 2 * tg;
                Sg[o]     = make_float2(S[nt][0], S[nt][2]);
                Sg[o + 1] = make_float2(S[nt][1], S[nt][3]);
            }
        }
    }
}

// ---------------- K4: inverse FFT; Re -> plus branch, Im -> minus branch ----------------
__global__ __launch_bounds__(1024) void k_ifft(float* __restrict__ out) {
    extern __shared__ float2 s[];
    const int b = blockIdx.x >> 6;
    const int o = blockIdx.x & 63;
    const float2* spb = g_Sp + (size_t)b * NF * DOUT + o;
    const float2* smb = g_Sm + (size_t)b * NF * DOUT + o;

    for (int f = threadIdx.x; f < NFFT; f += 1024) {
        float2 C;
        if (f <= L) {
            float2 p = spb[(size_t)f * DOUT];
            float2 m = smb[(size_t)f * DOUT];
            C = make_float2(p.x - m.y, p.y + m.x);
        } else {
            int gidx = NFFT - f;
            float2 p = spb[(size_t)gidx * DOUT];
            float2 m = smb[(size_t)gidx * DOUT];
            C = make_float2(p.x + m.y, m.x - p.y);
        }
        s[brev13(f)] = C;
    }
    __syncthreads();
    fft8192<1, 1024>(s);

    const float inv = 1.0f / (float)NFFT;
    float* ob = out + (size_t)b * L * DOUT + o;
    for (int t = threadIdx.x; t < L; t += 1024) {
        float2 c = s[t];
        float sg = (t & 1) ? -1.f : 1.f;
        ob[(size_t)t * DOUT] = inv * (c.x + sg * c.y);
    }
}

// ---------------- K5: autoregressive term ----------------
#define AR_T 128
__global__ __launch_bounds__(256)
void k_ar(const float* __restrict__ x, const float* __restrict__ M, float* __restrict__ out) {
    extern __shared__ float smar[];
    float* Ms = smar;            // [3][64][64]
    float* xs = smar + 12288;    // [130][64]

    const int b  = blockIdx.x >> 5;
    const int t0 = (blockIdx.x & 31) * AR_T;

    for (int idx = threadIdx.x; idx < 12288; idx += 256) {
        int o = idx / 192, r = idx - o * 192;
        int d = r / 3, i = r - d * 3;
        Ms[(i * 64 + d) * 64 + o] = M[idx];
    }
    for (int idx = threadIdx.x; idx < 130 * 64; idx += 256) {
        int r = idx >> 6, d = idx & 63;
        int t = t0 - 2 + r;
        xs[idx] = (t >= 0) ? x[((size_t)b * L + t) * DIN + d] : 0.f;
    }
    __syncthreads();

    const int o  = threadIdx.x & 63;
    const int tg = threadIdx.x >> 6;
    for (int tl = tg; tl < AR_T; tl += 4) {
        const float* x0 = xs + (tl + 2) * 64;
        const float* x1 = x0 - 64;
        const float* x2 = x0 - 128;
        float acc = 0.f;
        #pragma unroll
        for (int d = 0; d < 64; ++d) {
            acc += Ms[d * 64 + o]        * x0[d];
            acc += Ms[4096 + d * 64 + o] * x1[d];
            acc += Ms[8192 + d * 64 + o] * x2[d];
        }
        out[((size_t)b * L + t0 + tl) * DOUT + o] += acc;
    }
}

// ---------------- launch ----------------
extern "C" void kernel_launch(void* const* d_in, const int* in_sizes, int n_in,
                              void* d_out, int out_size) {
    const float* x   = (const float*)d_in[0];
    const float* phi = (const float*)d_in[1];
    const float* M   = (const float*)d_in[2];
    const float* Mp  = (const float*)d_in[3];
    const float* Mm  = (const float*)d_in[4];
    float* out = (float*)d_out;

    const int FFT_SMEM = NFFT * sizeof(float2);                       // 65536
    const int AR_SMEM  = (12288 + 130 * 64) * 4;                      // 82432
    const int EI_SMEM  = (128 * SA * 2 + 2 * 64 * SB + FE * KF * 2) * 4;  // 116736

    cudaFuncSetAttribute(k_fft_x,   cudaFuncAttributeMaxDynamicSharedMemorySize, FFT_SMEM);
    cudaFuncSetAttribute(k_fft_phi, cudaFuncAttributeMaxDynamicSharedMemorySize, FFT_SMEM);
    cudaFuncSetAttribute(k_ifft,    cudaFuncAttributeMaxDynamicSharedMemorySize, FFT_SMEM);
    cudaFuncSetAttribute(k_ar,      cudaFuncAttributeMaxDynamicSharedMemorySize, AR_SMEM);
    cudaFuncSetAttribute(k_einsum,  cudaFuncAttributeMaxDynamicSharedMemorySize, EI_SMEM);

    k_fft_x  <<<BSZ * (DIN / 2), 1024, FFT_SMEM>>>(x);
    k_fft_phi<<<KF / 2,          1024, FFT_SMEM>>>(phi);
    k_einsum <<<(NF + FE - 1) / FE, 256, EI_SMEM>>>(Mp, Mm);
    k_ifft   <<<BSZ * DOUT,      1024, FFT_SMEM>>>(out);
    k_ar     <<<BSZ * (L / AR_T), 256, AR_SMEM>>>(x, M, out);
}

// round 7
// speedup vs baseline: 1.6986x; 1.0016x over previous
#include <cuda_runtime.h>
#include <math.h>

// Problem constants
#define L     4096
#define NF    4097          // rfft bins for n=8192
#define NFFT  8192
#define DIN   64
#define DOUT  64
#define KF    40
#define BSZ   2
#define FE    32            // frequencies per einsum block

// ---------------- static device scratch (no allocations allowed) ----------------
__device__ float2 g_Xf[BSZ * NF * DIN];    // rfft of x
__device__ float2 g_vf[NF * KF];           // rfft of phi
__device__ float2 g_Sp[BSZ * NF * DOUT];   // plus-branch spectrum
__device__ float2 g_Sm[BSZ * NF * DOUT];   // minus-branch spectrum

// ---------------- helpers ----------------
__device__ __forceinline__ unsigned brev13(unsigned i) { return __brev(i) >> 19; }

__device__ __forceinline__ unsigned tf32cvt(float x) {
    unsigned r; asm("cvt.rna.tf32.f32 %0, %1;" : "=r"(r) : "f"(x)); return r;
}

__device__ __forceinline__ void mma_tf32(float& d0, float& d1, float& d2, float& d3,
                                         unsigned a0, unsigned a1, unsigned a2, unsigned a3,
                                         unsigned b0, unsigned b1) {
    asm("mma.sync.aligned.m16n8k8.row.col.f32.tf32.tf32.f32 "
        "{%0,%1,%2,%3},{%4,%5,%6,%7},{%8,%9},{%0,%1,%2,%3};"
        : "+f"(d0), "+f"(d1), "+f"(d2), "+f"(d3)
        : "r"(a0), "r"(a1), "r"(a2), "r"(a3), "r"(b0), "r"(b1));
}

// In-place radix-2 DIT FFT of length 8192 in shared memory (bit-reversed input).
template<int SIGN, int NT>
__device__ __forceinline__ void fft8192(float2* s) {
    #pragma unroll
    for (int st = 0; st < 13; ++st) {
        const int   half = 1 << st;
        const float ang  = (float)SIGN * 3.14159265358979323846f / (float)half;
        for (int j = threadIdx.x; j < 4096; j += NT) {
            int pos = j & (half - 1);
            int i0  = ((j >> st) << (st + 1)) + pos;
            int i1  = i0 + half;
            float sw, cw;
            __sincosf(ang * (float)pos, &sw, &cw);
            float2 u = s[i0], v = s[i1];
            float tr = cw * v.x - sw * v.y;
            float ti = cw * v.y + sw * v.x;
            s[i0] = make_float2(u.x + tr, u.y + ti);
            s[i1] = make_float2(u.x - tr, u.y - ti);
        }
        __syncthreads();
    }
}

// ---------------- K1: forward FFT of x (two real columns per complex FFT) ----------------
__global__ __launch_bounds__(1024) void k_fft_x(const float* __restrict__ x) {
    extern __shared__ float2 s[];
    const int b  = blockIdx.x >> 5;
    const int d0 = (blockIdx.x & 31) * 2;
    const float* xb = x + (size_t)b * L * DIN + d0;

    for (int i = threadIdx.x; i < NFFT; i += 1024) {
        float2 z = make_float2(0.f, 0.f);
        if (i < L) z = *(const float2*)(xb + (size_t)i * DIN);
        s[brev13(i)] = z;
    }
    __syncthreads();
    fft8192<-1, 1024>(s);

    float2* Xb = g_Xf + (size_t)b * NF * DIN;
    for (int f = threadIdx.x; f <= L; f += 1024) {
        float2 P = s[f];
        float2 Q = s[(NFFT - f) & (NFFT - 1)];
        float qr = Q.x, qi = -Q.y;
        float2 A  = make_float2(0.5f * (P.x + qr),  0.5f * (P.y + qi));
        float2 Bv = make_float2(0.5f * (P.y - qi), -0.5f * (P.x - qr));
        *(float4*)(&Xb[(size_t)f * DIN + d0]) = make_float4(A.x, A.y, Bv.x, Bv.y);
    }
}

// ---------------- K2: forward FFT of phi (two filters packed) ----------------
__global__ __launch_bounds__(1024) void k_fft_phi(const float* __restrict__ phi) {
    extern __shared__ float2 s[];
    const int k0 = blockIdx.x * 2;

    for (int i = threadIdx.x; i < NFFT; i += 1024) {
        float2 z = make_float2(0.f, 0.f);
        if (i < L) z = *(const float2*)(phi + (size_t)i * KF + k0);
        s[brev13(i)] = z;
    }
    __syncthreads();
    fft8192<-1, 1024>(s);

    for (int f = threadIdx.x; f <= L; f += 1024) {
        float2 P = s[f];
        float2 Q = s[(NFFT - f) & (NFFT - 1)];
        float qr = Q.x, qi = -Q.y;
        float2 A  = make_float2(0.5f * (P.x + qr),  0.5f * (P.y + qi));
        float2 Bv = make_float2(0.5f * (P.y - qi), -0.5f * (P.x - qr));
        *(float4*)(&g_vf[(size_t)f * KF + k0]) = make_float4(A.x, A.y, Bv.x, Bv.y);
    }
}

// ---------------- K3: frequency-domain contraction via tf32 mma.sync ----------------
// Sp[b,f,o] = sum_k vf[f,k] * sum_d Xf[b,f,d]        * Mp[k,d,o]
// Sm[b,f,o] = sum_k vf[f,k] * sum_d conj(Xf[b,L-f,d])* Mm[k,d,o]
//
// Per block: 32 freqs x 2 batches = 64 (b,f) pairs -> 128 GEMM rows ({re,im}).
// Row layout: warp w owns rows [16w,16w+16); within the 16-row tile, row q = re of
// pair 8w+q, row q+8 = im of same pair (so mma accum c0/c1 + c2/c3 form the re/im
// pair in ONE thread -> shuffle-free complex rotation by v[f,k] per k).
// X split into tf32 hi+lo (exact); M rounded to tf32 once.
#define SA 68   // A smem row stride (floats) — conflict-free frag loads
#define SB 72   // B smem row stride (floats) — conflict-free frag loads

__global__ __launch_bounds__(256, 1)
void k_einsum(const float* __restrict__ Mp, const float* __restrict__ Mm) {
    extern __shared__ float sm[];
    float*  Ah = sm;                       // [128][SA]
    float*  Al = Ah + 128 * SA;            // [128][SA]
    float*  Bs = Al + 128 * SA;            // [2][64][SB]
    float2* Vs = (float2*)(Bs + 2 * 64 * SB);  // [FE][KF]

    const int tid  = threadIdx.x;
    const int w    = tid >> 5;
    const int lane = tid & 31;
    const int g    = lane >> 2;      // 0..7
    const int tg   = lane & 3;       // 0..3
    const int f0   = blockIdx.x * FE;

    // stage V (complex filter spectra for this tile)
    for (int idx = tid; idx < FE * KF; idx += 256) {
        int fl = idx / KF, k = idx - fl * KF;
        int f  = f0 + fl;
        Vs[fl * KF + k] = (f <= L) ? g_vf[(size_t)f * KF + k] : make_float2(0.f, 0.f);
    }

    const int  p   = 8 * w + g;          // this thread's (b,f) pair
    const int  pfl = p & 31;
    const int  pb  = p >> 5;
    const int  pf  = f0 + pfl;
    const float2 zv = make_float2(0.f, 0.f);

    for (int br = 0; br < 2; ++br) {
        const float* Mb = br ? Mm : Mp;
        __syncthreads();                 // As reuse / Vs ready

        // ---- build split A in smem ----
        for (int idx = tid; idx < 64 * 64; idx += 256) {
            int pp = idx >> 6, d = idx & 63;
            int b  = pp >> 5, fl = pp & 31;
            int f  = f0 + fl;
            float re = 0.f, im = 0.f;
            if (f <= L) {
                float2 X;
                if (br == 0) { X = g_Xf[((size_t)b * NF + f) * DIN + d];       re = X.x; im = X.y;  }
                else         { X = g_Xf[((size_t)b * NF + (L - f)) * DIN + d]; re = X.x; im = -X.y; }
            }
            int rr = ((pp >> 3) << 4) + (pp & 7);     // re row
            unsigned hb = tf32cvt(re);
            float    hf = __uint_as_float(hb);
            unsigned lb = tf32cvt(re - hf);
            Ah[rr * SA + d] = hf;
            Al[rr * SA + d] = __uint_as_float(lb);
            hb = tf32cvt(im);
            hf = __uint_as_float(hb);
            lb = tf32cvt(im - hf);
            Ah[(rr + 8) * SA + d] = hf;
            Al[(rr + 8) * SA + d] = __uint_as_float(lb);
        }
        __syncthreads();

        // ---- load A fragments into registers (persist across k loop) ----
        unsigned ah[8][4], al[8][4];
        const int ar = w * 16 + g;
        #pragma unroll
        for (int ks = 0; ks < 8; ++ks) {
            int c = 8 * ks + tg;
            ah[ks][0] = __float_as_uint(Ah[ar * SA + c]);
            ah[ks][1] = __float_as_uint(Ah[(ar + 8) * SA + c]);
            ah[ks][2] = __float_as_uint(Ah[ar * SA + c + 4]);
            ah[ks][3] = __float_as_uint(Ah[(ar + 8) * SA + c + 4]);
            al[ks][0] = __float_as_uint(Al[ar * SA + c]);
            al[ks][1] = __float_as_uint(Al[(ar + 8) * SA + c]);
            al[ks][2] = __float_as_uint(Al[ar * SA + c + 4]);
            al[ks][3] = __float_as_uint(Al[(ar + 8) * SA + c + 4]);
        }

        float S[8][4];
        #pragma unroll
        for (int nt = 0; nt < 8; ++nt)
            S[nt][0] = S[nt][1] = S[nt][2] = S[nt][3] = 0.f;

        // ---- stage B for k=0 ----
        {
            const float* src = Mb;
            #pragma unroll
            for (int i = 0; i < 4; ++i) {
                int e = (tid + i * 256) * 4;
                float4 v4 = *(const float4*)(src + e);
                v4.x = __uint_as_float(tf32cvt(v4.x));
                v4.y = __uint_as_float(tf32cvt(v4.y));
                v4.z = __uint_as_float(tf32cvt(v4.z));
                v4.w = __uint_as_float(tf32cvt(v4.w));
                *(float4*)(&Bs[(e >> 6) * SB + (e & 63)]) = v4;
            }
        }
        __syncthreads();

        // ---- main k loop with double-buffered B ----
        for (int k = 0; k < KF; ++k) {
            const int cur = k & 1;
            float4 pf4[4];
            if (k + 1 < KF) {
                const float* src = Mb + (size_t)(k + 1) * 4096;
                #pragma unroll
                for (int i = 0; i < 4; ++i) {
                    int e = (tid + i * 256) * 4;
                    pf4[i] = *(const float4*)(src + e);
                }
            }

            const float* Bc = Bs + cur * 64 * SB;
            const float2 v  = (pf <= L) ? Vs[pfl * KF + k] : zv;

            #pragma unroll
            for (int nt = 0; nt < 8; ++nt) {
                float t0 = 0.f, t1 = 0.f, t2 = 0.f, t3 = 0.f;
                const int nc = 8 * nt + g;
                #pragma unroll
                for (int ks = 0; ks < 8; ++ks) {
                    unsigned b0 = __float_as_uint(Bc[(8 * ks + tg) * SB + nc]);
                    unsigned b1 = __float_as_uint(Bc[(8 * ks + tg + 4) * SB + nc]);
                    mma_tf32(t0, t1, t2, t3, ah[ks][0], ah[ks][1], ah[ks][2], ah[ks][3], b0, b1);
                    mma_tf32(t0, t1, t2, t3, al[ks][0], al[ks][1], al[ks][2], al[ks][3], b0, b1);
                }
                S[nt][0] += v.x * t0 - v.y * t2;
                S[nt][1] += v.x * t1 - v.y * t3;
                S[nt][2] += v.x * t2 + v.y * t0;
                S[nt][3] += v.x * t3 + v.y * t1;
            }

            if (k + 1 < KF) {
                float* Bn = Bs + (cur ^ 1) * 64 * SB;
                #pragma unroll
                for (int i = 0; i < 4; ++i) {
                    int e = (tid + i * 256) * 4;
                    float4 v4 = pf4[i];
                    v4.x = __uint_as_float(tf32cvt(v4.x));
                    v4.y = __uint_as_float(tf32cvt(v4.y));
                    v4.z = __uint_as_float(tf32cvt(v4.z));
                    v4.w = __uint_as_float(tf32cvt(v4.w));
                    *(float4*)(&Bn[(e >> 6) * SB + (e & 63)]) = v4;
                }
            }
            __syncthreads();
        }

        // ---- store S ----
        if (pf <= L) {
            float2* Sg = (br ? g_Sm : g_Sp) + ((size_t)pb * NF + pf) * DOUT;
            #pragma unroll
            for (int nt = 0; nt < 8; ++nt) {
                int o = 8 * nt + 2 * tg;
                Sg[o]     = make_float2(S[nt][0], S[nt][2]);
                Sg[o + 1] = make_float2(S[nt][1], S[nt][3]);
            }
        }
    }
}

// ---------------- K4: inverse FFT; Re -> plus branch, Im -> minus branch ----------------
__global__ __launch_bounds__(1024) void k_ifft(float* __restrict__ out) {
    extern __shared__ float2 s[];
    const int b = blockIdx.x >> 6;
    const int o = blockIdx.x & 63;
    const float2* spb = g_Sp + (size_t)b * NF * DOUT + o;
    const float2* smb = g_Sm + (size_t)b * NF * DOUT + o;

    for (int f = threadIdx.x; f < NFFT; f += 1024) {
        float2 C;
        if (f <= L) {
            float2 p = spb[(size_t)f * DOUT];
            float2 m = smb[(size_t)f * DOUT];
            C = make_float2(p.x - m.y, p.y + m.x);
        } else {
            int gidx = NFFT - f;
            float2 p = spb[(size_t)gidx * DOUT];
            float2 m = smb[(size_t)gidx * DOUT];
            C = make_float2(p.x + m.y, m.x - p.y);
        }
        s[brev13(f)] = C;
    }
    __syncthreads();
    fft8192<1, 1024>(s);

    const float inv = 1.0f / (float)NFFT;
    float* ob = out + (size_t)b * L * DOUT + o;
    for (int t = threadIdx.x; t < L; t += 1024) {
        float2 c = s[t];
        float sg = (t & 1) ? -1.f : 1.f;
        ob[(size_t)t * DOUT] = inv * (c.x + sg * c.y);
    }
}

// ---------------- K5: autoregressive term ----------------
#define AR_T 128
__global__ __launch_bounds__(256)
void k_ar(const float* __restrict__ x, const float* __restrict__ M, float* __restrict__ out) {
    extern __shared__ float smar[];
    float* Ms = smar;            // [3][64][64]
    float* xs = smar + 12288;    // [130][64]

    const int b  = blockIdx.x >> 5;
    const int t0 = (blockIdx.x & 31) * AR_T;

    for (int idx = threadIdx.x; idx < 12288; idx += 256) {
        int o = idx / 192, r = idx - o * 192;
        int d = r / 3, i = r - d * 3;
        Ms[(i * 64 + d) * 64 + o] = M[idx];
    }
    for (int idx = threadIdx.x; idx < 130 * 64; idx += 256) {
        int r = idx >> 6, d = idx & 63;
        int t = t0 - 2 + r;
        xs[idx] = (t >= 0) ? x[((size_t)b * L + t) * DIN + d] : 0.f;
    }
    __syncthreads();

    const int o  = threadIdx.x & 63;
    const int tg = threadIdx.x >> 6;
    for (int tl = tg; tl < AR_T; tl += 4) {
        const float* x0 = xs + (tl + 2) * 64;
        const float* x1 = x0 - 64;
        const float* x2 = x0 - 128;
        float acc = 0.f;
        #pragma unroll
        for (int d = 0; d < 64; ++d) {
            acc += Ms[d * 64 + o]        * x0[d];
            acc += Ms[4096 + d * 64 + o] * x1[d];
            acc += Ms[8192 + d * 64 + o] * x2[d];
        }
        out[((size_t)b * L + t0 + tl) * DOUT + o] += acc;
    }
}

// ---------------- launch ----------------
extern "C" void kernel_launch(void* const* d_in, const int* in_sizes, int n_in,
                              void* d_out, int out_size) {
    const float* x   = (const float*)d_in[0];
    const float* phi = (const float*)d_in[1];
    const float* M   = (const float*)d_in[2];
    const float* Mp  = (const float*)d_in[3];
    const float* Mm  = (const float*)d_in[4];
    float* out = (float*)d_out;

    const int FFT_SMEM = NFFT * sizeof(float2);                       // 65536
    const int AR_SMEM  = (12288 + 130 * 64) * 4;                      // 82432
    const int EI_SMEM  = (128 * SA * 2 + 2 * 64 * SB + FE * KF * 2) * 4;  // 116736

    cudaFuncSetAttribute(k_fft_x,   cudaFuncAttributeMaxDynamicSharedMemorySize, FFT_SMEM);
    cudaFuncSetAttribute(k_fft_phi, cudaFuncAttributeMaxDynamicSharedMemorySize, FFT_SMEM);
    cudaFuncSetAttribute(k_ifft,    cudaFuncAttributeMaxDynamicSharedMemorySize, FFT_SMEM);
    cudaFuncSetAttribute(k_ar,      cudaFuncAttributeMaxDynamicSharedMemorySize, AR_SMEM);
    cudaFuncSetAttribute(k_einsum,  cudaFuncAttributeMaxDynamicSharedMemorySize, EI_SMEM);

    k_fft_x  <<<BSZ * (DIN / 2), 1024, FFT_SMEM>>>(x);
    k_fft_phi<<<KF / 2,          1024, FFT_SMEM>>>(phi);
    k_einsum <<<(NF + FE - 1) / FE, 256, EI_SMEM>>>(Mp, Mm);
    k_ifft   <<<BSZ * DOUT,      1024, FFT_SMEM>>>(out);
    k_ar     <<<BSZ * (L / AR_T), 256, AR_SMEM>>>(x, M, out);
}

// round 9
// speedup vs baseline: 2.1774x; 1.2819x over previous
#include <cuda_runtime.h>
#include <cuda_fp16.h>
#include <math.h>

#define L     4096
#define NF    4097
#define NFFT  8192
#define KF    40
#define FE    32

// ---------------- static device scratch ----------------
__device__ float2 g_Xf[2 * NF * 64];
__device__ float2 g_vf[NF * KF];
__device__ float2 g_Sp[2 * NF * 64];
__device__ float2 g_Sm[2 * NF * 64];

// ---------------- helpers ----------------
__device__ __forceinline__ unsigned brev13(unsigned i) { return __brev(i) >> 19; }
__device__ __forceinline__ unsigned s2u(const void* p) { return (unsigned)__cvta_generic_to_shared(p); }

__device__ __forceinline__ void mma16(float& d0, float& d1, float& d2, float& d3,
                                      unsigned a0, unsigned a1, unsigned a2, unsigned a3,
                                      unsigned b0, unsigned b1) {
    asm("mma.sync.aligned.m16n8k16.row.col.f32.f16.f16.f32 "
        "{%0,%1,%2,%3},{%4,%5,%6,%7},{%8,%9},{%0,%1,%2,%3};"
        : "+f"(d0), "+f"(d1), "+f"(d2), "+f"(d3)
        : "r"(a0), "r"(a1), "r"(a2), "r"(a3), "r"(b0), "r"(b1));
}
__device__ __forceinline__ void ldsm4(unsigned* r, unsigned a) {
    asm volatile("ldmatrix.sync.aligned.m8n8.x4.shared.b16 {%0,%1,%2,%3}, [%4];"
                 : "=r"(r[0]), "=r"(r[1]), "=r"(r[2]), "=r"(r[3]) : "r"(a));
}
__device__ __forceinline__ void ldsm2t(unsigned& r0, unsigned& r1, unsigned a) {
    asm volatile("ldmatrix.sync.aligned.m8n8.x2.trans.shared.b16 {%0,%1}, [%2];"
                 : "=r"(r0), "=r"(r1) : "r"(a));
}

// In-place radix-2 FFT of 8192 (bit-reversed input) with shared twiddle table.
template<int NT>
__device__ __forceinline__ void fftT(float2* s, const float2* tw) {
    #pragma unroll
    for (int st = 0; st < 13; ++st) {
        const int half = 1 << st, sh = 12 - st;
        for (int j = threadIdx.x; j < 4096; j += NT) {
            int pos = j & (half - 1);
            int i0 = ((j >> st) << (st + 1)) + pos, i1 = i0 + half;
            float2 w = tw[pos << sh];
            float2 u = s[i0], v = s[i1];
            float tr = w.x * v.x - w.y * v.y;
            float ti = w.x * v.y + w.y * v.x;
            s[i0] = make_float2(u.x + tr, u.y + ti);
            s[i1] = make_float2(u.x - tr, u.y - ti);
        }
        __syncthreads();
    }
}

// ---------------- K1: forward FFTs of x (64 blocks) and phi (20 blocks) ----------------
__global__ __launch_bounds__(1024) void k_fwd(const float* __restrict__ x,
                                              const float* __restrict__ phi) {
    extern __shared__ float2 s[];
    float2* tw = s + NFFT;
    for (int i = threadIdx.x; i < 4096; i += 1024) {
        float sv, cv;
        __sincosf(3.14159265358979323846f * (float)i / 4096.0f, &sv, &cv);
        tw[i] = make_float2(cv, -sv);
    }
    const int bb = blockIdx.x;
    const float* src;
    int strd, c0;
    if (bb < 64) { int b = bb >> 5; c0 = (bb & 31) * 2; src = x + (size_t)b * L * 64 + c0; strd = 64; }
    else         { c0 = (bb - 64) * 2; src = phi + c0; strd = KF; }

    for (int i = threadIdx.x; i < NFFT; i += 1024) {
        float2 z = make_float2(0.f, 0.f);
        if (i < L) z = *(const float2*)(src + (size_t)i * strd);
        s[brev13(i)] = z;
    }
    __syncthreads();
    fftT<1024>(s, tw);

    for (int f = threadIdx.x; f <= L; f += 1024) {
        float2 P = s[f], Q = s[(NFFT - f) & (NFFT - 1)];
        float qr = Q.x, qi = -Q.y;
        float4 o = make_float4(0.5f * (P.x + qr), 0.5f * (P.y + qi),
                               0.5f * (P.y - qi), -0.5f * (P.x - qr));
        if (bb < 64) { int b = bb >> 5; *(float4*)&g_Xf[((size_t)b * NF + f) * 64 + c0] = o; }
        else         { *(float4*)&g_vf[(size_t)f * KF + c0] = o; }
    }
}

// ---------------- K3: frequency-domain contraction via fp16 m16n8k16 mma ----------------
// Rows: 64 (b,f) pairs x {re,im} = 128; re at row q, im at q+8 within each 16-row
// warp tile -> shuffle-free complex rotation by v[f,k] in the epilogue.
// X split hi+lo fp16 (exact to ~2^-22); M single-rounded fp16 (same mantissa as tf32).
#define SAH 72
#define SBH 72
#define OFF_AL 18432
#define OFF_B  36864
#define OFF_V  55296
#define EI_SMEM 65536

__global__ __launch_bounds__(256, 1)
void k_einsum(const float* __restrict__ Mp, const float* __restrict__ Mm) {
    extern __shared__ char smc[];
    __half* Ah = (__half*)smc;
    __half* Al = (__half*)(smc + OFF_AL);
    __half* Bs = (__half*)(smc + OFF_B);
    float2* Vs = (float2*)(smc + OFF_V);
    const unsigned smb = s2u(smc);
    const int tid = threadIdx.x, w = tid >> 5, lane = tid & 31, g = lane >> 2, tg = lane & 3;
    const int f0 = blockIdx.x * FE;

    for (int idx = tid; idx < FE * KF; idx += 256) {
        int fl = idx / KF, k = idx - fl * KF, f = f0 + fl;
        Vs[idx] = (f <= L) ? g_vf[(size_t)f * KF + k] : make_float2(0.f, 0.f);
    }

    const int p = 8 * w + g, pfl = p & 31, pb = p >> 5, pf = f0 + pfl;
    // ldmatrix lane address offsets (bytes)
    const unsigned aoff = 2u * ((unsigned)(w * 16 + ((lane >> 3) & 1) * 8 + (lane & 7)) * SAH
                                + (unsigned)(lane >> 4) * 8);
    const unsigned brow = (unsigned)((lane & 8) + (lane & 7));

    for (int br = 0; br < 2; ++br) {
        const float* Mb = br ? Mm : Mp;
        __syncthreads();

        // build split-fp16 A in smem
        for (int idx = tid; idx < 4096; idx += 256) {
            int pp = idx >> 6, d = idx & 63;
            int b = pp >> 5, fl = pp & 31, f = f0 + fl;
            float re = 0.f, im = 0.f;
            if (f <= L) {
                float2 X;
                if (br == 0) { X = g_Xf[((size_t)b * NF + f) * 64 + d];       re = X.x; im = X.y;  }
                else         { X = g_Xf[((size_t)b * NF + (L - f)) * 64 + d]; re = X.x; im = -X.y; }
            }
            int rr = ((pp >> 3) << 4) + (pp & 7);
            __half h = __float2half_rn(re);
            Ah[rr * SAH + d] = h;
            Al[rr * SAH + d] = __float2half_rn(re - __half2float(h));
            h = __float2half_rn(im);
            Ah[(rr + 8) * SAH + d] = h;
            Al[(rr + 8) * SAH + d] = __float2half_rn(im - __half2float(h));
        }
        __syncthreads();

        // A fragments (persist across k loop)
        unsigned ah[4][4], al[4][4];
        #pragma unroll
        for (int ks = 0; ks < 4; ++ks) {
            ldsm4(ah[ks], smb + aoff + 32u * ks);
            ldsm4(al[ks], smb + OFF_AL + aoff + 32u * ks);
        }

        float S[8][4];
        #pragma unroll
        for (int nt = 0; nt < 8; ++nt)
            S[nt][0] = S[nt][1] = S[nt][2] = S[nt][3] = 0.f;

        // stage B for k=0 into buf0
        #pragma unroll
        for (int i = 0; i < 4; ++i) {
            int e = (tid + i * 256) * 4;
            float4 v4 = *(const float4*)(Mb + e);
            __half2 p0 = __floats2half2_rn(v4.x, v4.y);
            __half2 p1 = __floats2half2_rn(v4.z, v4.w);
            *(uint2*)(Bs + (e >> 6) * SBH + (e & 63)) = make_uint2(*(unsigned*)&p0, *(unsigned*)&p1);
        }
        __syncthreads();

        for (int k = 0; k < KF; ++k) {
            const int cur = k & 1;
            float4 pf4[4];
            if (k + 1 < KF) {
                const float* src2 = Mb + (size_t)(k + 1) * 4096;
                #pragma unroll
                for (int i = 0; i < 4; ++i) pf4[i] = *(const float4*)(src2 + (tid + i * 256) * 4);
            }
            const unsigned bbase = smb + OFF_B + (unsigned)cur * 9216u;
            const float2 v = (pf <= L) ? Vs[pfl * KF + k] : make_float2(0.f, 0.f);

            #pragma unroll
            for (int nt = 0; nt < 8; ++nt) {
                float t0 = 0.f, t1 = 0.f, t2 = 0.f, t3 = 0.f;
                #pragma unroll
                for (int ks = 0; ks < 4; ++ks) {
                    unsigned b0, b1;
                    ldsm2t(b0, b1, bbase + 2u * ((16u * ks + brow) * SBH + 8u * nt));
                    mma16(t0, t1, t2, t3, ah[ks][0], ah[ks][1], ah[ks][2], ah[ks][3], b0, b1);
                    mma16(t0, t1, t2, t3, al[ks][0], al[ks][1], al[ks][2], al[ks][3], b0, b1);
                }
                S[nt][0] += v.x * t0 - v.y * t2;
                S[nt][1] += v.x * t1 - v.y * t3;
                S[nt][2] += v.x * t2 + v.y * t0;
                S[nt][3] += v.x * t3 + v.y * t1;
            }

            if (k + 1 < KF) {
                __half* Bn = Bs + (cur ^ 1) * 4608;
                #pragma unroll
                for (int i = 0; i < 4; ++i) {
                    int e = (tid + i * 256) * 4;
                    __half2 p0 = __floats2half2_rn(pf4[i].x, pf4[i].y);
                    __half2 p1 = __floats2half2_rn(pf4[i].z, pf4[i].w);
                    *(uint2*)(Bn + (e >> 6) * SBH + (e & 63)) = make_uint2(*(unsigned*)&p0, *(unsigned*)&p1);
                }
            }
            __syncthreads();
        }

        if (pf <= L) {
            float2* Sg = (br ? g_Sm : g_Sp) + ((size_t)pb * NF + pf) * 64;
            #pragma unroll
            for (int nt = 0; nt < 8; ++nt) {
                int o = 8 * nt + 2 * tg;
                Sg[o]     = make_float2(S[nt][0], S[nt][2]);
                Sg[o + 1] = make_float2(S[nt][1], S[nt][3]);
            }
        }
    }
}

// ---------------- K4: inverse FFT; Re -> plus, Im -> minus ----------------
__global__ __launch_bounds__(1024) void k_ifft(float* __restrict__ out) {
    extern __shared__ float2 s[];
    float2* tw = s + NFFT;
    for (int i = threadIdx.x; i < 4096; i += 1024) {
        float sv, cv;
        __sincosf(3.14159265358979323846f * (float)i / 4096.0f, &sv, &cv);
        tw[i] = make_float2(cv, sv);
    }
    const int b = blockIdx.x >> 6, o = blockIdx.x & 63;
    const float2* spb = g_Sp + (size_t)b * NF * 64 + o;
    const float2* smb = g_Sm + (size_t)b * NF * 64 + o;

    for (int f = threadIdx.x; f < NFFT; f += 1024) {
        float2 C;
        if (f <= L) {
            float2 p = spb[(size_t)f * 64], m = smb[(size_t)f * 64];
            C = make_float2(p.x - m.y, p.y + m.x);
        } else {
            int gi = NFFT - f;
            float2 p = spb[(size_t)gi * 64], m = smb[(size_t)gi * 64];
            C = make_float2(p.x + m.y, m.x - p.y);
        }
        s[brev13(f)] = C;
    }
    __syncthreads();
    fftT<1024>(s, tw);

    const float inv = 1.0f / 8192.0f;
    float* ob = out + (size_t)b * L * 64 + o;
    for (int t = threadIdx.x; t < L; t += 1024) {
        float2 c = s[t];
        ob[(size_t)t * 64] = inv * (c.x + ((t & 1) ? -c.y : c.y));
    }
}

// ---------------- K5: autoregressive term ----------------
#define AR_T 128
__global__ __launch_bounds__(256)
void k_ar(const float* __restrict__ x, const float* __restrict__ M, float* __restrict__ out) {
    extern __shared__ float smar[];
    float* Ms = smar;            // [3][64][64]
    float* xs = smar + 12288;    // [130][64]
    const int b = blockIdx.x >> 5;
    const int t0 = (blockIdx.x & 31) * AR_T;

    for (int idx = threadIdx.x; idx < 12288; idx += 256) {
        int o = idx / 192, r = idx - o * 192;
        int d = r / 3, i = r - d * 3;
        Ms[(i * 64 + d) * 64 + o] = M[idx];
    }
    for (int idx = threadIdx.x; idx < 130 * 64; idx += 256) {
        int r = idx >> 6, d = idx & 63;
        int t = t0 - 2 + r;
        xs[idx] = (t >= 0) ? x[((size_t)b * L + t) * 64 + d] : 0.f;
    }
    __syncthreads();

    const int o = threadIdx.x & 63;
    const int tg = threadIdx.x >> 6;
    for (int tl = tg; tl < AR_T; tl += 4) {
        const float* x0 = xs + (tl + 2) * 64;
        const float* x1 = x0 - 64;
        const float* x2 = x0 - 128;
        float acc = 0.f;
        #pragma unroll
        for (int d = 0; d < 64; ++d) {
            acc += Ms[d * 64 + o]        * x0[d];
            acc += Ms[4096 + d * 64 + o] * x1[d];
            acc += Ms[8192 + d * 64 + o] * x2[d];
        }
        out[((size_t)b * L + t0 + tl) * 64 + o] += acc;
    }
}

// ---------------- launch ----------------
extern "C" void kernel_launch(void* const* d_in, const int* in_sizes, int n_in,
                              void* d_out, int out_size) {
    const float* x   = (const float*)d_in[0];
    const float* phi = (const float*)d_in[1];
    const float* M   = (const float*)d_in[2];
    const float* Mp  = (const float*)d_in[3];
    const float* Mm  = (const float*)d_in[4];
    float* out = (float*)d_out;

    const int FFT_SMEM = (NFFT + 4096) * sizeof(float2);   // 98304
    const int AR_SMEM  = (12288 + 130 * 64) * 4;           // 82432

    cudaFuncSetAttribute(k_fwd,    cudaFuncAttributeMaxDynamicSharedMemorySize, FFT_SMEM);
    cudaFuncSetAttribute(k_ifft,   cudaFuncAttributeMaxDynamicSharedMemorySize, FFT_SMEM);
    cudaFuncSetAttribute(k_ar,     cudaFuncAttributeMaxDynamicSharedMemorySize, AR_SMEM);
    cudaFuncSetAttribute(k_einsum, cudaFuncAttributeMaxDynamicSharedMemorySize, EI_SMEM);

    k_fwd   <<<64 + KF / 2, 1024, FFT_SMEM>>>(x, phi);
    k_einsum<<<(NF + FE - 1) / FE, 256, EI_SMEM>>>(Mp, Mm);
    k_ifft  <<<2 * 64, 1024, FFT_SMEM>>>(out);
    k_ar    <<<2 * (L / AR_T), 256, AR_SMEM>>>(x, M, out);
}